// round 13
// baseline (speedup 1.0000x reference)
#include <cuda_runtime.h>
#include <math.h>

// ---------------- static problem config ----------------
#define BNN    8192
#define CC     64
#define KSEL   11
#define NLOC   1568
#define NROWS  1024

// ---------------- device scratch ----------------
__device__ float g_dists[(size_t)BNN * BNN];
__device__ float g_u[BNN * CC];
__device__ float g_sq[BNN];
__device__ int   g_inds[BNN * KSEL];
__device__ int   g_de[BNN];
__device__ float g_sknn[BNN * CC];
__device__ float g_sloc[NLOC * CC];
__device__ float g_z[BNN * CC];
__device__ float g_stats[2 * CC];
__device__ unsigned g_rowmin[(size_t)BNN * 64];   // per-(row, 128-col-chunk) min as ordkey

// ---------------- helpers ----------------
__device__ __forceinline__ int covdim(int r) {
    int lo = r - 4; if (lo < 0) lo = 0;
    int hi = r;     if (hi > 26) hi = 26;
    if (hi < lo) return 0;
    return hi / 2 - (lo + 1) / 2 + 1;
}

__device__ __forceinline__ float dv2f(int node) {
    int ln = node & (NROWS - 1);
    int r = ln >> 5, c = ln & 31;
    int deg = covdim(r) * covdim(c);
    return 1.0f / sqrtf((float)(KSEL + deg));
}

__device__ __forceinline__ unsigned ordkey(float f) {
    unsigned u = __float_as_uint(f);
    return (u & 0x80000000u) ? ~u : (u | 0x80000000u);
}
__device__ __forceinline__ float invordkey(unsigned k) {
    unsigned u = (k & 0x80000000u) ? (k ^ 0x80000000u) : ~k;
    return __uint_as_float(u);
}

#define KSENT 0xFF800000FFFFFFFFull

// packed f32x2 helpers
__device__ __forceinline__ void unpack2(unsigned long long v, float& lo, float& hi) {
    asm("mov.b64 {%0, %1}, %2;" : "=f"(lo), "=f"(hi) : "l"(v));
}
__device__ __forceinline__ void ffma2(unsigned long long& acc,
                                      unsigned long long a, unsigned long long b) {
    asm("fma.rn.f32x2 %0, %1, %2, %3;" : "=l"(acc) : "l"(a), "l"(b), "l"(acc));
}

// ---------------- kA: fused zero-init + sq norms + u = dv2 * (x W^T + b) ----------
// blocks [0, 2048): kA work on 4 nodes each; blocks [2048, 4096): zero accumulators
__global__ __launch_bounds__(256) void kA(const float* __restrict__ x,
                                          const float* __restrict__ W,
                                          const float* __restrict__ bconv) {
    int tid = threadIdx.x;
    if (blockIdx.x >= BNN / 4) {
        int i = (blockIdx.x - BNN / 4) * 256 + tid;   // 0 .. 524287
        g_sknn[i] = 0.0f;
        if (i < BNN)    g_de[i]    = 0;
        if (i < 2 * CC) g_stats[i] = 0.0f;
        return;
    }

    __shared__ float Ws[CC][CC + 1];
    __shared__ float xs[4][CC];
    __shared__ float red[256];
    int node0 = blockIdx.x * 4;

    for (int i = tid; i < CC * CC; i += 256) Ws[i >> 6][i & 63] = W[i];
    for (int i = tid; i < 4 * CC; i += 256) xs[i >> 6][i & 63] = x[node0 * CC + i];
    __syncthreads();

    int n = tid >> 6, c = tid & 63;
    int node = node0 + n;

    float v = xs[n][c];
    red[tid] = v * v;
    __syncthreads();
    if (c < 32) red[tid] += red[tid + 32]; __syncthreads();
    if (c < 16) red[tid] += red[tid + 16]; __syncthreads();
    if (c < 8)  red[tid] += red[tid + 8];  __syncthreads();
    if (c < 4)  red[tid] += red[tid + 4];  __syncthreads();
    if (c < 2)  red[tid] += red[tid + 2];  __syncthreads();
    if (c < 1)  red[tid] += red[tid + 1];  __syncthreads();
    if (c == 0) g_sq[node] = red[tid];

    float acc = bconv[c];
#pragma unroll
    for (int k = 0; k < CC; k++) acc += xs[n][k] * Ws[c][k];
    g_u[node * CC + c] = acc * dv2f(node);
}

// ---------------- kB: triangular-grid distance GEMM (FFMA2, dup-B) + mirror + chunk-min ----
// smem: As[64][130] floats, Bd[64][258] floats (B values duplicated in pairs);
//       Ts[128][129] reuses the same region for the transpose staging.
#define APAD 130
#define BPAD 258
#define SMEM_B_BYTES ((64 * APAD + 64 * BPAD) * 4)   // 99328

__global__ __launch_bounds__(256, 2) void kB(const float* __restrict__ x) {
    extern __shared__ float sm[];
    float (*As)[APAD] = (float (*)[APAD])sm;
    float (*Bd)[BPAD] = (float (*)[BPAD])(sm + 64 * APAD);
    float (*Ts)[129]  = (float (*)[129])sm;
    __shared__ unsigned sm_cm[128];

    // decode triangular tile index t -> (ib, jb), jb >= ib
    int t = blockIdx.x;
    int ib = (int)((129.0f - sqrtf(129.0f * 129.0f - 8.0f * (float)t)) * 0.5f);
    while (64 * ib - ib * (ib - 1) / 2 > t) ib--;
    while (64 * (ib + 1) - (ib + 1) * ib / 2 <= t) ib++;
    int jb = ib + (t - (64 * ib - ib * (ib - 1) / 2));

    int tid = threadIdx.x;
    if (tid < 128) sm_cm[tid] = 0xFFFFFFFFu;

#pragma unroll
    for (int it = 0; it < 8; it++) {
        int idx = tid + it * 256;
        int r   = idx >> 4;
        int k4  = (idx & 15) * 4;
        float4 va = *(const float4*)(x + (size_t)(ib * 128 + r) * CC + k4);
        As[k4 + 0][r] = va.x; As[k4 + 1][r] = va.y;
        As[k4 + 2][r] = va.z; As[k4 + 3][r] = va.w;
        float4 vb = *(const float4*)(x + (size_t)(jb * 128 + r) * CC + k4);
        *(float2*)&Bd[k4 + 0][2 * r] = make_float2(vb.x, vb.x);
        *(float2*)&Bd[k4 + 1][2 * r] = make_float2(vb.y, vb.y);
        *(float2*)&Bd[k4 + 2][2 * r] = make_float2(vb.z, vb.z);
        *(float2*)&Bd[k4 + 3][2 * r] = make_float2(vb.w, vb.w);
    }
    __syncthreads();

    int tx = tid & 31;
    int ty = tid >> 5;

    unsigned long long acc2[8][4];
#pragma unroll
    for (int i = 0; i < 8; i++)
#pragma unroll
        for (int j = 0; j < 4; j++) acc2[i][j] = 0ull;

#pragma unroll 4
    for (int k = 0; k < 64; k++) {
        unsigned long long a2[8];
#pragma unroll
        for (int i = 0; i < 8; i++)
            a2[i] = *(const unsigned long long*)&As[k][ty * 16 + 2 * i];
        unsigned long long b2[4];
#pragma unroll
        for (int j = 0; j < 4; j++)
            b2[j] = *(const unsigned long long*)&Bd[k][2 * (tx + 32 * j)];
#pragma unroll
        for (int i = 0; i < 8; i++)
#pragma unroll
            for (int j = 0; j < 4; j++) ffma2(acc2[i][j], a2[i], b2[j]);
    }

    float sqj[4];
#pragma unroll
    for (int j = 0; j < 4; j++) sqj[j] = g_sq[jb * 128 + tx + 32 * j];

#pragma unroll
    for (int i = 0; i < 8; i++) {
        int r0 = ty * 16 + 2 * i;
        float sq0 = g_sq[ib * 128 + r0];
        float sq1 = g_sq[ib * 128 + r0 + 1];
        size_t ro0 = (size_t)(ib * 128 + r0) * BNN;
        size_t ro1 = ro0 + BNN;
        float rm0 = __uint_as_float(0x7f800000u);
        float rm1 = rm0;
#pragma unroll
        for (int j = 0; j < 4; j++) {
            float lo, hi;
            unpack2(acc2[i][j], lo, hi);
            lo = sq0 + sqj[j] - 2.0f * lo;
            hi = sq1 + sqj[j] - 2.0f * hi;
            int col = jb * 128 + tx + 32 * j;
            g_dists[ro0 + col] = lo;
            g_dists[ro1 + col] = hi;
            rm0 = fminf(rm0, lo);
            rm1 = fminf(rm1, hi);
            asm("mov.b64 %0, {%1, %2};" : "=l"(acc2[i][j]) : "f"(lo), "f"(hi));
        }
#pragma unroll
        for (int off = 16; off; off >>= 1) {
            rm0 = fminf(rm0, __shfl_xor_sync(0xffffffffu, rm0, off));
            rm1 = fminf(rm1, __shfl_xor_sync(0xffffffffu, rm1, off));
        }
        if (tx == 0) {
            g_rowmin[((size_t)(ib * 128 + r0)) * 64 + jb]     = ordkey(rm0);
            g_rowmin[((size_t)(ib * 128 + r0 + 1)) * 64 + jb] = ordkey(rm1);
        }
    }

    if (jb > ib) {
        __syncthreads();   // done reading As/Bd; sm_cm init visible
#pragma unroll
        for (int j = 0; j < 4; j++) {
            float cmv = __uint_as_float(0x7f800000u);
#pragma unroll
            for (int i = 0; i < 8; i++) {
                float lo, hi;
                unpack2(acc2[i][j], lo, hi);
                cmv = fminf(cmv, fminf(lo, hi));
                Ts[ty * 16 + 2 * i][tx + 32 * j]     = lo;
                Ts[ty * 16 + 2 * i + 1][tx + 32 * j] = hi;
            }
            atomicMin(&sm_cm[tx + 32 * j], ordkey(cmv));
        }
        __syncthreads();
#pragma unroll
        for (int i = 0; i < 16; i++) {
            int cp = ty * 16 + i;
            size_t rowoff = (size_t)(jb * 128 + cp) * BNN;
#pragma unroll
            for (int j = 0; j < 4; j++) {
                int rp = tx + 32 * j;
                g_dists[rowoff + ib * 128 + rp] = Ts[rp][cp];
            }
        }
        if (tid < 128)
            g_rowmin[((size_t)(jb * 128 + tid)) * 64 + ib] = sm_cm[tid];
    }
}

// ---------------- kC: warp-per-row top-11, ordered-chunk candidates ----------------
#define PROC_CHUNK(CCH, FV)                                                        \
    do {                                                                           \
        float f_[4] = {(FV).x, (FV).y, (FV).z, (FV).w};                            \
        _Pragma("unroll")                                                          \
        for (int q_ = 0; q_ < 4; q_++) {                                           \
            unsigned mm_ = __ballot_sync(0xffffffffu, f_[q_] <= worstf);           \
            while (mm_) {                                                          \
                int src_ = __ffs(mm_) - 1;                                         \
                mm_ &= mm_ - 1;                                                    \
                float fv_ = __shfl_sync(0xffffffffu, f_[q_], src_);                \
                unsigned long long key_ =                                          \
                    ((unsigned long long)ordkey(fv_) << 32) |                      \
                    (unsigned)((CCH) * 128 + src_ * 4 + q_);                       \
                if (key_ < L[KSEL - 1]) {                                          \
                    L[KSEL - 1] = key_;                                            \
                    _Pragma("unroll")                                              \
                    for (int p_ = KSEL - 1; p_ > 0; --p_) {                        \
                        unsigned long long a_ = L[p_ - 1], b_ = L[p_];             \
                        bool sw_ = b_ < a_;                                        \
                        L[p_ - 1] = sw_ ? b_ : a_;                                 \
                        L[p_]     = sw_ ? a_ : b_;                                 \
                    }                                                              \
                    worstf = fminf(invordkey((unsigned)(L[KSEL - 1] >> 32)), Tuf); \
                }                                                                  \
            }                                                                      \
        }                                                                          \
    } while (0)

__global__ __launch_bounds__(256) void kC() {
    __shared__ unsigned scm[8][64];
    int w    = threadIdx.x >> 5;
    int row  = blockIdx.x * 8 + w;
    int lane = threadIdx.x & 31;

    const float4* Drow = (const float4*)(g_dists + (size_t)row * BNN);

    unsigned c0 = g_rowmin[(size_t)row * 64 + lane];
    unsigned c1 = g_rowmin[(size_t)row * 64 + 32 + lane];
    scm[w][lane]      = c0;
    scm[w][lane + 32] = c1;
    __syncwarp();

    // phase 1: pop the 11 smallest chunkmins
    int order[KSEL];
    unsigned Tu = 0xFFFFFFFFu;
    {
        unsigned x0 = c0, x1 = c1;
#pragma unroll
        for (int m = 0; m < KSEL; m++) {
            unsigned lm = x0 < x1 ? x0 : x1;
#pragma unroll
            for (int off = 16; off; off >>= 1) {
                unsigned o = __shfl_xor_sync(0xffffffffu, lm, off);
                lm = o < lm ? o : lm;
            }
            unsigned b0 = __ballot_sync(0xffffffffu, x0 == lm);
            int chunk;
            if (b0) {
                chunk = __ffs(b0) - 1;
                if (lane == chunk) x0 = 0xFFFFFFFFu;
            } else {
                unsigned b1 = __ballot_sync(0xffffffffu, x1 == lm);
                chunk = 32 + __ffs(b1) - 1;
                if (lane == chunk - 32) x1 = 0xFFFFFFFFu;
            }
            order[m] = chunk;
            Tu = lm;
        }
    }
    float Tuf = invordkey(Tu);

    // phase 2: parallel-load the 11 best chunks, process in quality order
    float4 fa[KSEL];
#pragma unroll
    for (int m = 0; m < KSEL; m++)
        fa[m] = __ldcs(&Drow[order[m] * 32 + lane]);

    unsigned long long L[KSEL];
#pragma unroll
    for (int s = 0; s < KSEL; s++) L[s] = KSENT;
    float worstf = Tuf;

#pragma unroll
    for (int m = 0; m < KSEL; m++) {
        unsigned wk = (unsigned)(L[KSEL - 1] >> 32);
        if (scm[w][order[m]] > wk) continue;
        PROC_CHUNK(order[m], fa[m]);
    }

    // phase 3: tie-exactness — rescan unvisited chunks with chunkmin <= worst key
    {
        unsigned long long vis = 0ull;
#pragma unroll
        for (int m = 0; m < KSEL; m++) vis |= 1ull << order[m];
        unsigned wk = (unsigned)(L[KSEL - 1] >> 32);
        bool need0 = (c0 <= wk) && !((vis >> lane) & 1ull);
        bool need1 = (c1 <= wk) && !((vis >> (lane + 32)) & 1ull);
        unsigned nb0 = __ballot_sync(0xffffffffu, need0);
        unsigned nb1 = __ballot_sync(0xffffffffu, need1);
        while (nb0) {
            int c = __ffs(nb0) - 1; nb0 &= nb0 - 1;
            float4 v = __ldcs(&Drow[c * 32 + lane]);
            PROC_CHUNK(c, v);
        }
        while (nb1) {
            int c = 32 + __ffs(nb1) - 1; nb1 &= nb1 - 1;
            float4 v = __ldcs(&Drow[c * 32 + lane]);
            PROC_CHUNK(c, v);
        }
    }

    if (lane < KSEL) {
        int idx;
#pragma unroll
        for (int p = 0; p < KSEL; p++)
            if (p == lane) idx = (int)(L[p] & 0xffffffffu);
        g_inds[row * KSEL + lane] = idx;
        atomicAdd(&g_de[idx], 1);
    }
}

// ---------------- kScat: fused KNN scatter + local edge sums ----------------
// blocks [0, 2048): scatter; blocks [2048, 2440): local edges (4 per block)
__global__ __launch_bounds__(256) void kScat() {
    int tid = threadIdx.x;
    if (blockIdx.x >= BNN / 4) {
        int e = (blockIdx.x - BNN / 4) * 4 + (tid >> 6);
        int c = tid & 63;
        if (e < NLOC) {
            int b  = e / 196, le = e % 196;
            int er = le / 14, ec = le % 14;
            int base = b * NROWS + er * 2 * 32 + ec * 2;
            float s = 0.0f;
#pragma unroll
            for (int dr = 0; dr < 5; dr++)
#pragma unroll
                for (int dc = 0; dc < 5; dc++)
                    s += g_u[(base + dr * 32 + dc) * CC + c];
            g_sloc[e * CC + c] = s * (1.0f / 25.0f);
        }
        return;
    }

    __shared__ int si[4 * KSEL];
    int node0 = blockIdx.x * 4;
    if (tid < 4 * KSEL) si[tid] = g_inds[node0 * KSEL + tid];
    __syncthreads();
    int n = tid >> 6, c = tid & 63;
    float uv = g_u[(node0 + n) * CC + c];
#pragma unroll
    for (int m = 0; m < KSEL; m++)
        atomicAdd(&g_sknn[si[n * KSEL + m] * CC + c], uv);
}

// ---------------- kE: gather z (with fused 1/DE) + BN stats ----------------
__global__ __launch_bounds__(256) void kE() {
    __shared__ int si[4 * KSEL];
    __shared__ float sdr[4 * KSEL];
    __shared__ float red[256], red2[256];
    int tid = threadIdx.x;
    int node0 = blockIdx.x * 4;
    if (tid < 4 * KSEL) si[tid] = g_inds[node0 * KSEL + tid];
    __syncthreads();
    if (tid < 4 * KSEL) sdr[tid] = 1.0f / (float)g_de[si[tid]];
    __syncthreads();
    int n = tid >> 6, c = tid & 63;
    int node = node0 + n;

    float acc = 0.0f;
#pragma unroll
    for (int m = 0; m < KSEL; m++)
        acc += g_sknn[si[n * KSEL + m] * CC + c] * sdr[n * KSEL + m];

    int ln = node & (NROWS - 1);
    int r = ln >> 5, cc2 = ln & 31;
    int b = node >> 10;
    int sr0 = r - 4; if (sr0 < 0) sr0 = 0; sr0 += (sr0 & 1);
    int sr1 = r;     if (sr1 > 26) sr1 = 26; sr1 -= (sr1 & 1);
    int sc0 = cc2 - 4; if (sc0 < 0) sc0 = 0; sc0 += (sc0 & 1);
    int sc1 = cc2;     if (sc1 > 26) sc1 = 26; sc1 -= (sc1 & 1);
    for (int sr = sr0; sr <= sr1; sr += 2)
        for (int sc = sc0; sc <= sc1; sc += 2)
            acc += g_sloc[(b * 196 + (sr >> 1) * 14 + (sc >> 1)) * CC + c];

    float z = acc * dv2f(node);
    g_z[node * CC + c] = z;

    red[tid] = z; red2[tid] = z * z;
    __syncthreads();
    if (tid < 128) { red[tid] += red[tid + 128]; red2[tid] += red2[tid + 128]; }
    __syncthreads();
    if (tid < 64) {
        atomicAdd(&g_stats[tid],      red[tid]  + red[tid + 64]);
        atomicAdd(&g_stats[64 + tid], red2[tid] + red2[tid + 64]);
    }
}

// ---------------- kG ----------------
__global__ void kG(const float* __restrict__ x,
                   const float* __restrict__ gamma,
                   const float* __restrict__ beta,
                   float* __restrict__ out) {
    int i = blockIdx.x * 256 + threadIdx.x;
    int c = i & 63;
    float mu  = g_stats[c]      * (1.0f / (float)BNN);
    float ex2 = g_stats[64 + c] * (1.0f / (float)BNN);
    float var = ex2 - mu * mu;
    float rstd = 1.0f / sqrtf(var + 1e-5f);
    float zn = (g_z[i] - mu) * rstd * gamma[c] + beta[c];
    out[i] = fmaxf(zn, 0.0f) + x[i];
}

// ---------------- launch ----------------
extern "C" void kernel_launch(void* const* d_in, const int* in_sizes, int n_in,
                              void* d_out, int out_size) {
    const float* x     = (const float*)d_in[0];
    const float* W     = (const float*)d_in[1];
    const float* bconv = (const float*)d_in[2];
    const float* gamma = (const float*)d_in[3];
    const float* beta  = (const float*)d_in[4];
    float* out = (float*)d_out;

    cudaFuncSetAttribute(kB, cudaFuncAttributeMaxDynamicSharedMemorySize, SMEM_B_BYTES);

    kA    <<<BNN / 4 + 2048, 256>>>(x, W, bconv);
    kB    <<<2080, 256, SMEM_B_BYTES>>>(x);
    kC    <<<BNN / 8, 256>>>();
    kScat <<<BNN / 4 + 392, 256>>>();
    kE    <<<BNN / 4, 256>>>();
    kG    <<<2048, 256>>>(x, gamma, beta, out);
}

// round 14
// speedup vs baseline: 1.2429x; 1.2429x over previous
#include <cuda_runtime.h>
#include <cuda_bf16.h>
#include <math.h>
#include <stdint.h>

// ---------------- static problem config ----------------
#define BNN    8192
#define CC     64
#define KSEL   11
#define NLOC   1568
#define NROWS  1024

// ---------------- device scratch ----------------
__device__ float g_dists[(size_t)BNN * BNN];
__device__ float g_u[BNN * CC];
__device__ float g_sq[BNN];
__device__ int   g_inds[BNN * KSEL];
__device__ int   g_de[BNN];
__device__ float g_sknn[BNN * CC];
__device__ float g_sloc[NLOC * CC];
__device__ float g_z[BNN * CC];
__device__ float g_stats[2 * CC];
__device__ unsigned g_rowmin[(size_t)BNN * 64];

// ---------------- helpers ----------------
__device__ __forceinline__ int covdim(int r) {
    int lo = r - 4; if (lo < 0) lo = 0;
    int hi = r;     if (hi > 26) hi = 26;
    if (hi < lo) return 0;
    return hi / 2 - (lo + 1) / 2 + 1;
}

__device__ __forceinline__ float dv2f(int node) {
    int ln = node & (NROWS - 1);
    int r = ln >> 5, c = ln & 31;
    int deg = covdim(r) * covdim(c);
    return 1.0f / sqrtf((float)(KSEL + deg));
}

__device__ __forceinline__ unsigned ordkey(float f) {
    unsigned u = __float_as_uint(f);
    return (u & 0x80000000u) ? ~u : (u | 0x80000000u);
}
__device__ __forceinline__ float invordkey(unsigned k) {
    unsigned u = (k & 0x80000000u) ? (k ^ 0x80000000u) : ~k;
    return __uint_as_float(u);
}

#define KSENT 0xFF800000FFFFFFFFull

__device__ __forceinline__ uint32_t smem_u32(const void* p) {
    uint32_t a;
    asm("{ .reg .u64 t; cvta.to.shared.u64 t, %1; cvt.u32.u64 %0, t; }"
        : "=r"(a) : "l"(p));
    return a;
}

__device__ __forceinline__ void ldsm4(uint32_t* r, uint32_t addr) {
    asm volatile("ldmatrix.sync.aligned.m8n8.x4.shared.b16 {%0,%1,%2,%3}, [%4];"
        : "=r"(r[0]), "=r"(r[1]), "=r"(r[2]), "=r"(r[3]) : "r"(addr));
}

__device__ __forceinline__ void mma_bf16(float* d, const uint32_t* a,
                                         uint32_t b0, uint32_t b1) {
    asm volatile("mma.sync.aligned.m16n8k16.row.col.f32.bf16.bf16.f32 "
        "{%0,%1,%2,%3}, {%4,%5,%6,%7}, {%8,%9}, {%0,%1,%2,%3};"
        : "+f"(d[0]), "+f"(d[1]), "+f"(d[2]), "+f"(d[3])
        : "r"(a[0]), "r"(a[1]), "r"(a[2]), "r"(a[3]), "r"(b0), "r"(b1));
}

__device__ __forceinline__ uint32_t pk(__nv_bfloat16 a, __nv_bfloat16 b) {
    __nv_bfloat162 t = __halves2bfloat162(a, b);
    return *(uint32_t*)&t;
}

// ---------------- kA: fused zero-init + sq norms + u ----------------
__global__ __launch_bounds__(256) void kA(const float* __restrict__ x,
                                          const float* __restrict__ W,
                                          const float* __restrict__ bconv) {
    int tid = threadIdx.x;
    if (blockIdx.x >= BNN / 4) {
        int i = (blockIdx.x - BNN / 4) * 256 + tid;
        g_sknn[i] = 0.0f;
        if (i < BNN)    g_de[i]    = 0;
        if (i < 2 * CC) g_stats[i] = 0.0f;
        return;
    }

    __shared__ float Ws[CC][CC + 1];
    __shared__ float xs[4][CC];
    __shared__ float red[256];
    int node0 = blockIdx.x * 4;

    for (int i = tid; i < CC * CC; i += 256) Ws[i >> 6][i & 63] = W[i];
    for (int i = tid; i < 4 * CC; i += 256) xs[i >> 6][i & 63] = x[node0 * CC + i];
    __syncthreads();

    int n = tid >> 6, c = tid & 63;
    int node = node0 + n;

    float v = xs[n][c];
    red[tid] = v * v;
    __syncthreads();
    if (c < 32) red[tid] += red[tid + 32]; __syncthreads();
    if (c < 16) red[tid] += red[tid + 16]; __syncthreads();
    if (c < 8)  red[tid] += red[tid + 8];  __syncthreads();
    if (c < 4)  red[tid] += red[tid + 4];  __syncthreads();
    if (c < 2)  red[tid] += red[tid + 2];  __syncthreads();
    if (c < 1)  red[tid] += red[tid + 1];  __syncthreads();
    if (c == 0) g_sq[node] = red[tid];

    float acc = bconv[c];
#pragma unroll
    for (int k = 0; k < CC; k++) acc += xs[n][k] * Ws[c][k];
    g_u[node * CC + c] = acc * dv2f(node);
}

// ---------------- kB: bf16x3 mma.sync distance GEMM (triangle + mirror + chunkmin) ----
// smem: 4 bf16 operand arrays [128][72] (Ab1 Ab2 Bb1 Bb2) = 73728B, sqj floats at 73728
// Ts[128][129] floats reuses the operand region in the epilogue.
#define OPSROW 72
#define OPSZ   (128 * OPSROW * 2)        // 18432 B per array
#define SQJOFF (4 * OPSZ)                // 73728
#define SMEM_KB (SQJOFF + 512)

__global__ __launch_bounds__(256, 2) void kB(const float* __restrict__ x) {
    extern __shared__ char sm[];
    uint32_t smb = smem_u32(sm);
    __nv_bfloat16* Ab1 = (__nv_bfloat16*)sm;
    __nv_bfloat16* Ab2 = Ab1 + 128 * OPSROW;
    __nv_bfloat16* Bb1 = Ab2 + 128 * OPSROW;
    __nv_bfloat16* Bb2 = Bb1 + 128 * OPSROW;
    float* sqjs = (float*)(sm + SQJOFF);
    float (*Ts)[129] = (float (*)[129])sm;

    // triangular tile decode
    int t = blockIdx.x;
    int ib = (int)((129.0f - sqrtf(129.0f * 129.0f - 8.0f * (float)t)) * 0.5f);
    while (64 * ib - ib * (ib - 1) / 2 > t) ib--;
    while (64 * (ib + 1) - (ib + 1) * ib / 2 <= t) ib++;
    int jb = ib + (t - (64 * ib - ib * (ib - 1) / 2));

    int tid = threadIdx.x;
    int w = tid >> 5, lane = tid & 31;

    if (tid < 128) sqjs[tid] = g_sq[jb * 128 + tid];

    // split loader: 2048 float4-groups (128 rows x 16 groups), both sides
    for (int it = tid; it < 2048; it += 256) {
        int r = it >> 4, q = it & 15;
        int off = r * OPSROW + q * 4;
        {
            float4 va = *(const float4*)(x + (size_t)(ib * 128 + r) * CC + q * 4);
            __nv_bfloat16 hx = __float2bfloat16_rn(va.x), hy = __float2bfloat16_rn(va.y);
            __nv_bfloat16 hz = __float2bfloat16_rn(va.z), hw = __float2bfloat16_rn(va.w);
            *(uint2*)(Ab1 + off) = make_uint2(pk(hx, hy), pk(hz, hw));
            __nv_bfloat16 lx = __float2bfloat16_rn(va.x - __bfloat162float(hx));
            __nv_bfloat16 ly = __float2bfloat16_rn(va.y - __bfloat162float(hy));
            __nv_bfloat16 lz = __float2bfloat16_rn(va.z - __bfloat162float(hz));
            __nv_bfloat16 lw = __float2bfloat16_rn(va.w - __bfloat162float(hw));
            *(uint2*)(Ab2 + off) = make_uint2(pk(lx, ly), pk(lz, lw));
        }
        {
            float4 vb = *(const float4*)(x + (size_t)(jb * 128 + r) * CC + q * 4);
            __nv_bfloat16 hx = __float2bfloat16_rn(vb.x), hy = __float2bfloat16_rn(vb.y);
            __nv_bfloat16 hz = __float2bfloat16_rn(vb.z), hw = __float2bfloat16_rn(vb.w);
            *(uint2*)(Bb1 + off) = make_uint2(pk(hx, hy), pk(hz, hw));
            __nv_bfloat16 lx = __float2bfloat16_rn(vb.x - __bfloat162float(hx));
            __nv_bfloat16 ly = __float2bfloat16_rn(vb.y - __bfloat162float(hy));
            __nv_bfloat16 lz = __float2bfloat16_rn(vb.z - __bfloat162float(hz));
            __nv_bfloat16 lw = __float2bfloat16_rn(vb.w - __bfloat162float(hw));
            *(uint2*)(Bb2 + off) = make_uint2(pk(lx, ly), pk(lz, lw));
        }
    }
    __syncthreads();

    float acc[16][4];
#pragma unroll
    for (int i = 0; i < 16; i++)
#pragma unroll
        for (int j = 0; j < 4; j++) acc[i][j] = 0.0f;

    uint32_t aA1 = smb + 0 * OPSZ, aA2 = smb + 1 * OPSZ;
    uint32_t aB1 = smb + 2 * OPSZ, aB2 = smb + 3 * OPSZ;

#pragma unroll
    for (int kk = 0; kk < 4; kk++) {
        int lrow = w * 16 + (lane & 15);
        int lcol = kk * 16 + (lane >> 4) * 8;
        uint32_t aoff = (uint32_t)(lrow * OPSROW + lcol) * 2;
        uint32_t a1[4], a2[4];
        ldsm4(a1, aA1 + aoff);
        ldsm4(a2, aA2 + aoff);
#pragma unroll
        for (int tp = 0; tp < 8; tp++) {
            int brow = tp * 16 + (lane & 15);
            uint32_t boff = (uint32_t)(brow * OPSROW + lcol) * 2;
            uint32_t b1r[4], b2r[4];
            ldsm4(b1r, aB1 + boff);
            ldsm4(b2r, aB2 + boff);
            mma_bf16(acc[2 * tp],     a1, b1r[0], b1r[2]);
            mma_bf16(acc[2 * tp + 1], a1, b1r[1], b1r[3]);
            mma_bf16(acc[2 * tp],     a1, b2r[0], b2r[2]);
            mma_bf16(acc[2 * tp + 1], a1, b2r[1], b2r[3]);
            mma_bf16(acc[2 * tp],     a2, b1r[0], b1r[2]);
            mma_bf16(acc[2 * tp + 1], a2, b1r[1], b1r[3]);
        }
    }
    __syncthreads();   // operand reads done; Ts may now overwrite

    // epilogue: distances -> Ts, rowmins from regs
    {
        int qr = lane >> 2, qc = lane & 3;
        int row_lo = w * 16 + qr, row_hi = row_lo + 8;
        float sqi_lo = g_sq[ib * 128 + row_lo];
        float sqi_hi = g_sq[ib * 128 + row_hi];
        float rml = __uint_as_float(0x7f800000u), rmh = rml;
#pragma unroll
        for (int tt = 0; tt < 16; tt++) {
            int c0 = tt * 8 + qc * 2;
            float sj0 = sqjs[c0], sj1 = sqjs[c0 + 1];
            float v0 = sqi_lo + sj0 - 2.0f * acc[tt][0];
            float v1 = sqi_lo + sj1 - 2.0f * acc[tt][1];
            float v2 = sqi_hi + sj0 - 2.0f * acc[tt][2];
            float v3 = sqi_hi + sj1 - 2.0f * acc[tt][3];
            Ts[row_lo][c0] = v0; Ts[row_lo][c0 + 1] = v1;
            Ts[row_hi][c0] = v2; Ts[row_hi][c0 + 1] = v3;
            rml = fminf(rml, fminf(v0, v1));
            rmh = fminf(rmh, fminf(v2, v3));
        }
        rml = fminf(rml, __shfl_xor_sync(0xffffffffu, rml, 1));
        rml = fminf(rml, __shfl_xor_sync(0xffffffffu, rml, 2));
        rmh = fminf(rmh, __shfl_xor_sync(0xffffffffu, rmh, 1));
        rmh = fminf(rmh, __shfl_xor_sync(0xffffffffu, rmh, 2));
        if (qc == 0) {
            g_rowmin[((size_t)(ib * 128 + row_lo)) * 64 + jb] = ordkey(rml);
            g_rowmin[((size_t)(ib * 128 + row_hi)) * 64 + jb] = ordkey(rmh);
        }
    }
    __syncthreads();

    // direct coalesced store
#pragma unroll 4
    for (int it = 0; it < 64; it++) {
        int row = it * 2 + (tid >> 7);
        int col = tid & 127;
        g_dists[(size_t)(ib * 128 + row) * BNN + jb * 128 + col] = Ts[row][col];
    }

    if (jb > ib) {
        if (tid < 128) {
            float cm = __uint_as_float(0x7f800000u);
#pragma unroll 8
            for (int r = 0; r < 128; r++) cm = fminf(cm, Ts[r][tid]);
            g_rowmin[((size_t)(jb * 128 + tid)) * 64 + ib] = ordkey(cm);
        }
#pragma unroll 4
        for (int it = 0; it < 64; it++) {
            int cp = it * 2 + (tid >> 7);
            int rp = tid & 127;
            g_dists[(size_t)(jb * 128 + cp) * BNN + ib * 128 + rp] = Ts[rp][cp];
        }
    }
}

// ---------------- kC: warp-per-row top-11, ordered-chunk candidates ----------------
#define PROC_CHUNK(CCH, FV)                                                        \
    do {                                                                           \
        float f_[4] = {(FV).x, (FV).y, (FV).z, (FV).w};                            \
        _Pragma("unroll")                                                          \
        for (int q_ = 0; q_ < 4; q_++) {                                           \
            unsigned mm_ = __ballot_sync(0xffffffffu, f_[q_] <= worstf);           \
            while (mm_) {                                                          \
                int src_ = __ffs(mm_) - 1;                                         \
                mm_ &= mm_ - 1;                                                    \
                float fv_ = __shfl_sync(0xffffffffu, f_[q_], src_);                \
                unsigned long long key_ =                                          \
                    ((unsigned long long)ordkey(fv_) << 32) |                      \
                    (unsigned)((CCH) * 128 + src_ * 4 + q_);                       \
                if (key_ < L[KSEL - 1]) {                                          \
                    L[KSEL - 1] = key_;                                            \
                    _Pragma("unroll")                                              \
                    for (int p_ = KSEL - 1; p_ > 0; --p_) {                        \
                        unsigned long long a_ = L[p_ - 1], b_ = L[p_];             \
                        bool sw_ = b_ < a_;                                        \
                        L[p_ - 1] = sw_ ? b_ : a_;                                 \
                        L[p_]     = sw_ ? a_ : b_;                                 \
                    }                                                              \
                    worstf = fminf(invordkey((unsigned)(L[KSEL - 1] >> 32)), Tuf); \
                }                                                                  \
            }                                                                      \
        }                                                                          \
    } while (0)

__global__ __launch_bounds__(256) void kC() {
    __shared__ unsigned scm[8][64];
    int w    = threadIdx.x >> 5;
    int row  = blockIdx.x * 8 + w;
    int lane = threadIdx.x & 31;

    const float4* Drow = (const float4*)(g_dists + (size_t)row * BNN);

    unsigned c0 = g_rowmin[(size_t)row * 64 + lane];
    unsigned c1 = g_rowmin[(size_t)row * 64 + 32 + lane];
    scm[w][lane]      = c0;
    scm[w][lane + 32] = c1;
    __syncwarp();

    int order[KSEL];
    unsigned Tu = 0xFFFFFFFFu;
    {
        unsigned x0 = c0, x1 = c1;
#pragma unroll
        for (int m = 0; m < KSEL; m++) {
            unsigned lm = x0 < x1 ? x0 : x1;
#pragma unroll
            for (int off = 16; off; off >>= 1) {
                unsigned o = __shfl_xor_sync(0xffffffffu, lm, off);
                lm = o < lm ? o : lm;
            }
            unsigned b0 = __ballot_sync(0xffffffffu, x0 == lm);
            int chunk;
            if (b0) {
                chunk = __ffs(b0) - 1;
                if (lane == chunk) x0 = 0xFFFFFFFFu;
            } else {
                unsigned b1 = __ballot_sync(0xffffffffu, x1 == lm);
                chunk = 32 + __ffs(b1) - 1;
                if (lane == chunk - 32) x1 = 0xFFFFFFFFu;
            }
            order[m] = chunk;
            Tu = lm;
        }
    }
    float Tuf = invordkey(Tu);

    float4 fa[KSEL];
#pragma unroll
    for (int m = 0; m < KSEL; m++)
        fa[m] = __ldcs(&Drow[order[m] * 32 + lane]);

    unsigned long long L[KSEL];
#pragma unroll
    for (int s = 0; s < KSEL; s++) L[s] = KSENT;
    float worstf = Tuf;

#pragma unroll
    for (int m = 0; m < KSEL; m++) {
        unsigned wk = (unsigned)(L[KSEL - 1] >> 32);
        if (scm[w][order[m]] > wk) continue;
        PROC_CHUNK(order[m], fa[m]);
    }

    {
        unsigned long long vis = 0ull;
#pragma unroll
        for (int m = 0; m < KSEL; m++) vis |= 1ull << order[m];
        unsigned wk = (unsigned)(L[KSEL - 1] >> 32);
        bool need0 = (c0 <= wk) && !((vis >> lane) & 1ull);
        bool need1 = (c1 <= wk) && !((vis >> (lane + 32)) & 1ull);
        unsigned nb0 = __ballot_sync(0xffffffffu, need0);
        unsigned nb1 = __ballot_sync(0xffffffffu, need1);
        while (nb0) {
            int c = __ffs(nb0) - 1; nb0 &= nb0 - 1;
            float4 v = __ldcs(&Drow[c * 32 + lane]);
            PROC_CHUNK(c, v);
        }
        while (nb1) {
            int c = 32 + __ffs(nb1) - 1; nb1 &= nb1 - 1;
            float4 v = __ldcs(&Drow[c * 32 + lane]);
            PROC_CHUNK(c, v);
        }
    }

    if (lane < KSEL) {
        int idx;
#pragma unroll
        for (int p = 0; p < KSEL; p++)
            if (p == lane) idx = (int)(L[p] & 0xffffffffu);
        g_inds[row * KSEL + lane] = idx;
        atomicAdd(&g_de[idx], 1);
    }
}

// ---------------- kScat: fused KNN scatter + local edge sums ----------------
__global__ __launch_bounds__(256) void kScat() {
    int tid = threadIdx.x;
    if (blockIdx.x >= BNN / 4) {
        int e = (blockIdx.x - BNN / 4) * 4 + (tid >> 6);
        int c = tid & 63;
        if (e < NLOC) {
            int b  = e / 196, le = e % 196;
            int er = le / 14, ec = le % 14;
            int base = b * NROWS + er * 2 * 32 + ec * 2;
            float s = 0.0f;
#pragma unroll
            for (int dr = 0; dr < 5; dr++)
#pragma unroll
                for (int dc = 0; dc < 5; dc++)
                    s += g_u[(base + dr * 32 + dc) * CC + c];
            g_sloc[e * CC + c] = s * (1.0f / 25.0f);
        }
        return;
    }

    __shared__ int si[4 * KSEL];
    int node0 = blockIdx.x * 4;
    if (tid < 4 * KSEL) si[tid] = g_inds[node0 * KSEL + tid];
    __syncthreads();
    int n = tid >> 6, c = tid & 63;
    float uv = g_u[(node0 + n) * CC + c];
#pragma unroll
    for (int m = 0; m < KSEL; m++)
        atomicAdd(&g_sknn[si[n * KSEL + m] * CC + c], uv);
}

// ---------------- kE: gather z (fused 1/DE) + BN stats ----------------
__global__ __launch_bounds__(256) void kE() {
    __shared__ int si[4 * KSEL];
    __shared__ float sdr[4 * KSEL];
    __shared__ float red[256], red2[256];
    int tid = threadIdx.x;
    int node0 = blockIdx.x * 4;
    if (tid < 4 * KSEL) si[tid] = g_inds[node0 * KSEL + tid];
    __syncthreads();
    if (tid < 4 * KSEL) sdr[tid] = 1.0f / (float)g_de[si[tid]];
    __syncthreads();
    int n = tid >> 6, c = tid & 63;
    int node = node0 + n;

    float acc = 0.0f;
#pragma unroll
    for (int m = 0; m < KSEL; m++)
        acc += g_sknn[si[n * KSEL + m] * CC + c] * sdr[n * KSEL + m];

    int ln = node & (NROWS - 1);
    int r = ln >> 5, cc2 = ln & 31;
    int b = node >> 10;
    int sr0 = r - 4; if (sr0 < 0) sr0 = 0; sr0 += (sr0 & 1);
    int sr1 = r;     if (sr1 > 26) sr1 = 26; sr1 -= (sr1 & 1);
    int sc0 = cc2 - 4; if (sc0 < 0) sc0 = 0; sc0 += (sc0 & 1);
    int sc1 = cc2;     if (sc1 > 26) sc1 = 26; sc1 -= (sc1 & 1);
    for (int sr = sr0; sr <= sr1; sr += 2)
        for (int sc = sc0; sc <= sc1; sc += 2)
            acc += g_sloc[(b * 196 + (sr >> 1) * 14 + (sc >> 1)) * CC + c];

    float z = acc * dv2f(node);
    g_z[node * CC + c] = z;

    red[tid] = z; red2[tid] = z * z;
    __syncthreads();
    if (tid < 128) { red[tid] += red[tid + 128]; red2[tid] += red2[tid + 128]; }
    __syncthreads();
    if (tid < 64) {
        atomicAdd(&g_stats[tid],      red[tid]  + red[tid + 64]);
        atomicAdd(&g_stats[64 + tid], red2[tid] + red2[tid + 64]);
    }
}

// ---------------- kG ----------------
__global__ void kG(const float* __restrict__ x,
                   const float* __restrict__ gamma,
                   const float* __restrict__ beta,
                   float* __restrict__ out) {
    int i = blockIdx.x * 256 + threadIdx.x;
    int c = i & 63;
    float mu  = g_stats[c]      * (1.0f / (float)BNN);
    float ex2 = g_stats[64 + c] * (1.0f / (float)BNN);
    float var = ex2 - mu * mu;
    float rstd = 1.0f / sqrtf(var + 1e-5f);
    float zn = (g_z[i] - mu) * rstd * gamma[c] + beta[c];
    out[i] = fmaxf(zn, 0.0f) + x[i];
}

// ---------------- launch ----------------
extern "C" void kernel_launch(void* const* d_in, const int* in_sizes, int n_in,
                              void* d_out, int out_size) {
    const float* x     = (const float*)d_in[0];
    const float* W     = (const float*)d_in[1];
    const float* bconv = (const float*)d_in[2];
    const float* gamma = (const float*)d_in[3];
    const float* beta  = (const float*)d_in[4];
    float* out = (float*)d_out;

    cudaFuncSetAttribute(kB, cudaFuncAttributeMaxDynamicSharedMemorySize, SMEM_KB);

    kA    <<<BNN / 4 + 2048, 256>>>(x, W, bconv);
    kB    <<<2080, 256, SMEM_KB>>>(x);
    kC    <<<BNN / 8, 256>>>();
    kScat <<<BNN / 4 + 392, 256>>>();
    kE    <<<BNN / 4, 256>>>();
    kG    <<<2048, 256>>>(x, gamma, beta, out);
}

// round 16
// speedup vs baseline: 1.2593x; 1.0132x over previous
#include <cuda_runtime.h>
#include <cuda_bf16.h>
#include <math.h>
#include <stdint.h>

// ---------------- static problem config ----------------
#define BNN    8192
#define CC     64
#define KSEL   11
#define NLOC   1568
#define NROWS  1024

// ---------------- device scratch ----------------
__device__ float g_dists[(size_t)BNN * BNN];
__device__ float g_u[BNN * CC];
__device__ float g_sq[BNN];
__device__ int   g_inds[BNN * KSEL];
__device__ int   g_de[BNN];
__device__ float g_sknn[BNN * CC];
__device__ float g_sloc[NLOC * CC];
__device__ float g_z[BNN * CC];
__device__ float g_stats[2 * CC];
__device__ unsigned g_rowmin[(size_t)BNN * 64];

// ---------------- helpers ----------------
__device__ __forceinline__ int covdim(int r) {
    int lo = r - 4; if (lo < 0) lo = 0;
    int hi = r;     if (hi > 26) hi = 26;
    if (hi < lo) return 0;
    return hi / 2 - (lo + 1) / 2 + 1;
}

__device__ __forceinline__ float dv2f(int node) {
    int ln = node & (NROWS - 1);
    int r = ln >> 5, c = ln & 31;
    int deg = covdim(r) * covdim(c);
    return 1.0f / sqrtf((float)(KSEL + deg));
}

__device__ __forceinline__ unsigned ordkey(float f) {
    unsigned u = __float_as_uint(f);
    return (u & 0x80000000u) ? ~u : (u | 0x80000000u);
}
__device__ __forceinline__ float invordkey(unsigned k) {
    unsigned u = (k & 0x80000000u) ? (k ^ 0x80000000u) : ~k;
    return __uint_as_float(u);
}

#define KSENT 0xFF800000FFFFFFFFull

__device__ __forceinline__ uint32_t smem_u32(const void* p) {
    uint32_t a;
    asm("{ .reg .u64 t; cvta.to.shared.u64 t, %1; cvt.u32.u64 %0, t; }"
        : "=r"(a) : "l"(p));
    return a;
}

__device__ __forceinline__ void ldsm4(uint32_t* r, uint32_t addr) {
    asm volatile("ldmatrix.sync.aligned.m8n8.x4.shared.b16 {%0,%1,%2,%3}, [%4];"
        : "=r"(r[0]), "=r"(r[1]), "=r"(r[2]), "=r"(r[3]) : "r"(addr));
}

__device__ __forceinline__ void mma_bf16(float* d, const uint32_t* a,
                                         uint32_t b0, uint32_t b1) {
    asm volatile("mma.sync.aligned.m16n8k16.row.col.f32.bf16.bf16.f32 "
        "{%0,%1,%2,%3}, {%4,%5,%6,%7}, {%8,%9}, {%0,%1,%2,%3};"
        : "+f"(d[0]), "+f"(d[1]), "+f"(d[2]), "+f"(d[3])
        : "r"(a[0]), "r"(a[1]), "r"(a[2]), "r"(a[3]), "r"(b0), "r"(b1));
}

__device__ __forceinline__ uint32_t pk(__nv_bfloat16 a, __nv_bfloat16 b) {
    __nv_bfloat162 t = __halves2bfloat162(a, b);
    return *(uint32_t*)&t;
}

// ---------------- kA: fused zero-init + sq norms + u ----------------
__global__ __launch_bounds__(256) void kA(const float* __restrict__ x,
                                          const float* __restrict__ W,
                                          const float* __restrict__ bconv) {
    int tid = threadIdx.x;
    if (blockIdx.x >= BNN / 4) {
        int i = (blockIdx.x - BNN / 4) * 256 + tid;
        g_sknn[i] = 0.0f;
        if (i < BNN)    g_de[i]    = 0;
        if (i < 2 * CC) g_stats[i] = 0.0f;
        return;
    }

    __shared__ float Ws[CC][CC + 1];
    __shared__ float xs[4][CC];
    __shared__ float red[256];
    int node0 = blockIdx.x * 4;

    for (int i = tid; i < CC * CC; i += 256) Ws[i >> 6][i & 63] = W[i];
    for (int i = tid; i < 4 * CC; i += 256) xs[i >> 6][i & 63] = x[node0 * CC + i];
    __syncthreads();

    int n = tid >> 6, c = tid & 63;
    int node = node0 + n;

    float v = xs[n][c];
    red[tid] = v * v;
    __syncthreads();
    if (c < 32) red[tid] += red[tid + 32]; __syncthreads();
    if (c < 16) red[tid] += red[tid + 16]; __syncthreads();
    if (c < 8)  red[tid] += red[tid + 8];  __syncthreads();
    if (c < 4)  red[tid] += red[tid + 4];  __syncthreads();
    if (c < 2)  red[tid] += red[tid + 2];  __syncthreads();
    if (c < 1)  red[tid] += red[tid + 1];  __syncthreads();
    if (c == 0) g_sq[node] = red[tid];

    float acc = bconv[c];
#pragma unroll
    for (int k = 0; k < CC; k++) acc += xs[n][k] * Ws[c][k];
    g_u[node * CC + c] = acc * dv2f(node);
}

// ---------------- kB: bf16x3 mma.sync distance GEMM (triangle + mirror + chunkmin) ----
#define OPSROW 72
#define OPSZ   (128 * OPSROW * 2)
#define SQJOFF (4 * OPSZ)
#define SMEM_KB (SQJOFF + 512)

__global__ __launch_bounds__(256, 2) void kB(const float* __restrict__ x) {
    extern __shared__ char sm[];
    uint32_t smb = smem_u32(sm);
    __nv_bfloat16* Ab1 = (__nv_bfloat16*)sm;
    __nv_bfloat16* Ab2 = Ab1 + 128 * OPSROW;
    __nv_bfloat16* Bb1 = Ab2 + 128 * OPSROW;
    __nv_bfloat16* Bb2 = Bb1 + 128 * OPSROW;
    float* sqjs = (float*)(sm + SQJOFF);
    float (*Ts)[129] = (float (*)[129])sm;

    int t = blockIdx.x;
    int ib = (int)((129.0f - sqrtf(129.0f * 129.0f - 8.0f * (float)t)) * 0.5f);
    while (64 * ib - ib * (ib - 1) / 2 > t) ib--;
    while (64 * (ib + 1) - (ib + 1) * ib / 2 <= t) ib++;
    int jb = ib + (t - (64 * ib - ib * (ib - 1) / 2));

    int tid = threadIdx.x;
    int w = tid >> 5, lane = tid & 31;

    if (tid < 128) sqjs[tid] = g_sq[jb * 128 + tid];

    for (int it = tid; it < 2048; it += 256) {
        int r = it >> 4, q = it & 15;
        int off = r * OPSROW + q * 4;
        {
            float4 va = *(const float4*)(x + (size_t)(ib * 128 + r) * CC + q * 4);
            __nv_bfloat16 hx = __float2bfloat16_rn(va.x), hy = __float2bfloat16_rn(va.y);
            __nv_bfloat16 hz = __float2bfloat16_rn(va.z), hw = __float2bfloat16_rn(va.w);
            *(uint2*)(Ab1 + off) = make_uint2(pk(hx, hy), pk(hz, hw));
            __nv_bfloat16 lx = __float2bfloat16_rn(va.x - __bfloat162float(hx));
            __nv_bfloat16 ly = __float2bfloat16_rn(va.y - __bfloat162float(hy));
            __nv_bfloat16 lz = __float2bfloat16_rn(va.z - __bfloat162float(hz));
            __nv_bfloat16 lw = __float2bfloat16_rn(va.w - __bfloat162float(hw));
            *(uint2*)(Ab2 + off) = make_uint2(pk(lx, ly), pk(lz, lw));
        }
        {
            float4 vb = *(const float4*)(x + (size_t)(jb * 128 + r) * CC + q * 4);
            __nv_bfloat16 hx = __float2bfloat16_rn(vb.x), hy = __float2bfloat16_rn(vb.y);
            __nv_bfloat16 hz = __float2bfloat16_rn(vb.z), hw = __float2bfloat16_rn(vb.w);
            *(uint2*)(Bb1 + off) = make_uint2(pk(hx, hy), pk(hz, hw));
            __nv_bfloat16 lx = __float2bfloat16_rn(vb.x - __bfloat162float(hx));
            __nv_bfloat16 ly = __float2bfloat16_rn(vb.y - __bfloat162float(hy));
            __nv_bfloat16 lz = __float2bfloat16_rn(vb.z - __bfloat162float(hz));
            __nv_bfloat16 lw = __float2bfloat16_rn(vb.w - __bfloat162float(hw));
            *(uint2*)(Bb2 + off) = make_uint2(pk(lx, ly), pk(lz, lw));
        }
    }
    __syncthreads();

    float acc[16][4];
#pragma unroll
    for (int i = 0; i < 16; i++)
#pragma unroll
        for (int j = 0; j < 4; j++) acc[i][j] = 0.0f;

    uint32_t aA1 = smb + 0 * OPSZ, aA2 = smb + 1 * OPSZ;
    uint32_t aB1 = smb + 2 * OPSZ, aB2 = smb + 3 * OPSZ;

#pragma unroll
    for (int kk = 0; kk < 4; kk++) {
        int lrow = w * 16 + (lane & 15);
        int lcol = kk * 16 + (lane >> 4) * 8;
        uint32_t aoff = (uint32_t)(lrow * OPSROW + lcol) * 2;
        uint32_t a1[4], a2[4];
        ldsm4(a1, aA1 + aoff);
        ldsm4(a2, aA2 + aoff);
#pragma unroll
        for (int tp = 0; tp < 8; tp++) {
            int brow = tp * 16 + (lane & 15);
            uint32_t boff = (uint32_t)(brow * OPSROW + lcol) * 2;
            uint32_t b1r[4], b2r[4];
            ldsm4(b1r, aB1 + boff);
            ldsm4(b2r, aB2 + boff);
            mma_bf16(acc[2 * tp],     a1, b1r[0], b1r[2]);
            mma_bf16(acc[2 * tp + 1], a1, b1r[1], b1r[3]);
            mma_bf16(acc[2 * tp],     a1, b2r[0], b2r[2]);
            mma_bf16(acc[2 * tp + 1], a1, b2r[1], b2r[3]);
            mma_bf16(acc[2 * tp],     a2, b1r[0], b1r[2]);
            mma_bf16(acc[2 * tp + 1], a2, b1r[1], b1r[3]);
        }
    }
    __syncthreads();

    {
        int qr = lane >> 2, qc = lane & 3;
        int row_lo = w * 16 + qr, row_hi = row_lo + 8;
        float sqi_lo = g_sq[ib * 128 + row_lo];
        float sqi_hi = g_sq[ib * 128 + row_hi];
        float rml = __uint_as_float(0x7f800000u), rmh = rml;
#pragma unroll
        for (int tt = 0; tt < 16; tt++) {
            int c0 = tt * 8 + qc * 2;
            float sj0 = sqjs[c0], sj1 = sqjs[c0 + 1];
            float v0 = sqi_lo + sj0 - 2.0f * acc[tt][0];
            float v1 = sqi_lo + sj1 - 2.0f * acc[tt][1];
            float v2 = sqi_hi + sj0 - 2.0f * acc[tt][2];
            float v3 = sqi_hi + sj1 - 2.0f * acc[tt][3];
            Ts[row_lo][c0] = v0; Ts[row_lo][c0 + 1] = v1;
            Ts[row_hi][c0] = v2; Ts[row_hi][c0 + 1] = v3;
            rml = fminf(rml, fminf(v0, v1));
            rmh = fminf(rmh, fminf(v2, v3));
        }
        rml = fminf(rml, __shfl_xor_sync(0xffffffffu, rml, 1));
        rml = fminf(rml, __shfl_xor_sync(0xffffffffu, rml, 2));
        rmh = fminf(rmh, __shfl_xor_sync(0xffffffffu, rmh, 1));
        rmh = fminf(rmh, __shfl_xor_sync(0xffffffffu, rmh, 2));
        if (qc == 0) {
            g_rowmin[((size_t)(ib * 128 + row_lo)) * 64 + jb] = ordkey(rml);
            g_rowmin[((size_t)(ib * 128 + row_hi)) * 64 + jb] = ordkey(rmh);
        }
    }
    __syncthreads();

#pragma unroll 4
    for (int it = 0; it < 64; it++) {
        int row = it * 2 + (tid >> 7);
        int col = tid & 127;
        g_dists[(size_t)(ib * 128 + row) * BNN + jb * 128 + col] = Ts[row][col];
    }

    if (jb > ib) {
        if (tid < 128) {
            float cm = __uint_as_float(0x7f800000u);
#pragma unroll 8
            for (int r = 0; r < 128; r++) cm = fminf(cm, Ts[r][tid]);
            g_rowmin[((size_t)(jb * 128 + tid)) * 64 + ib] = ordkey(cm);
        }
#pragma unroll 4
        for (int it = 0; it < 64; it++) {
            int cp = it * 2 + (tid >> 7);
            int rp = tid & 127;
            g_dists[(size_t)(jb * 128 + cp) * BNN + ib * 128 + rp] = Ts[rp][cp];
        }
    }
}

// ---------------- kC: warp-per-row top-11, cp.async-staged candidates ----------------
#define PROC_CHUNK(CCH, FV)                                                        \
    do {                                                                           \
        float f_[4] = {(FV).x, (FV).y, (FV).z, (FV).w};                            \
        _Pragma("unroll")                                                          \
        for (int q_ = 0; q_ < 4; q_++) {                                           \
            unsigned mm_ = __ballot_sync(0xffffffffu, f_[q_] <= worstf);           \
            while (mm_) {                                                          \
                int src_ = __ffs(mm_) - 1;                                         \
                mm_ &= mm_ - 1;                                                    \
                float fv_ = __shfl_sync(0xffffffffu, f_[q_], src_);                \
                unsigned long long key_ =                                          \
                    ((unsigned long long)ordkey(fv_) << 32) |                      \
                    (unsigned)((CCH) * 128 + src_ * 4 + q_);                       \
                if (key_ < L[KSEL - 1]) {                                          \
                    L[KSEL - 1] = key_;                                            \
                    _Pragma("unroll")                                              \
                    for (int p_ = KSEL - 1; p_ > 0; --p_) {                        \
                        unsigned long long a_ = L[p_ - 1], b_ = L[p_];             \
                        bool sw_ = b_ < a_;                                        \
                        L[p_ - 1] = sw_ ? b_ : a_;                                 \
                        L[p_]     = sw_ ? a_ : b_;                                 \
                    }                                                              \
                    worstf = fminf(invordkey((unsigned)(L[KSEL - 1] >> 32)), Tuf); \
                }                                                                  \
            }                                                                      \
        }                                                                          \
    } while (0)

#define KC_WARPS 2
__global__ __launch_bounds__(32 * KC_WARPS) void kC() {
    __shared__ unsigned scm[KC_WARPS][64];
    __shared__ float4 buf[KC_WARPS][KSEL][32];   // staged candidate chunks
    int w    = threadIdx.x >> 5;
    int row  = blockIdx.x * KC_WARPS + w;
    int lane = threadIdx.x & 31;

    const float4* Drow = (const float4*)(g_dists + (size_t)row * BNN);

    unsigned c0 = g_rowmin[(size_t)row * 64 + lane];
    unsigned c1 = g_rowmin[(size_t)row * 64 + 32 + lane];
    scm[w][lane]      = c0;
    scm[w][lane + 32] = c1;
    __syncwarp();

    // phase 1: pop the 11 smallest chunkmins
    int order[KSEL];
    unsigned Tu = 0xFFFFFFFFu;
    {
        unsigned x0 = c0, x1 = c1;
#pragma unroll
        for (int m = 0; m < KSEL; m++) {
            unsigned lm = x0 < x1 ? x0 : x1;
#pragma unroll
            for (int off = 16; off; off >>= 1) {
                unsigned o = __shfl_xor_sync(0xffffffffu, lm, off);
                lm = o < lm ? o : lm;
            }
            unsigned b0 = __ballot_sync(0xffffffffu, x0 == lm);
            int chunk;
            if (b0) {
                chunk = __ffs(b0) - 1;
                if (lane == chunk) x0 = 0xFFFFFFFFu;
            } else {
                unsigned b1 = __ballot_sync(0xffffffffu, x1 == lm);
                chunk = 32 + __ffs(b1) - 1;
                if (lane == chunk - 32) x1 = 0xFFFFFFFFu;
            }
            order[m] = chunk;
            Tu = lm;
        }
    }
    float Tuf = invordkey(Tu);

    // phase 2: cp.async-stage the 11 best chunks (lane reads back only its own 16B)
#pragma unroll
    for (int m = 0; m < KSEL; m++) {
        uint32_t dst = smem_u32(&buf[w][m][lane]);
        const float4* src = &Drow[order[m] * 32 + lane];
        asm volatile("cp.async.cg.shared.global [%0], [%1], 16;"
                     :: "r"(dst), "l"(src) : "memory");
    }
    asm volatile("cp.async.commit_group;" ::: "memory");
    asm volatile("cp.async.wait_group 0;" ::: "memory");

    unsigned long long L[KSEL];
#pragma unroll
    for (int s = 0; s < KSEL; s++) L[s] = KSENT;
    float worstf = Tuf;

#pragma unroll
    for (int m = 0; m < KSEL; m++) {
        unsigned wk = (unsigned)(L[KSEL - 1] >> 32);
        if (scm[w][order[m]] > wk) continue;
        float4 v = buf[w][m][lane];
        PROC_CHUNK(order[m], v);
    }

    // phase 3: tie-exactness — rescan unvisited chunks with chunkmin <= worst key
    {
        unsigned long long vis = 0ull;
#pragma unroll
        for (int m = 0; m < KSEL; m++) vis |= 1ull << order[m];
        unsigned wk = (unsigned)(L[KSEL - 1] >> 32);
        bool need0 = (c0 <= wk) && !((vis >> lane) & 1ull);
        bool need1 = (c1 <= wk) && !((vis >> (lane + 32)) & 1ull);
        unsigned nb0 = __ballot_sync(0xffffffffu, need0);
        unsigned nb1 = __ballot_sync(0xffffffffu, need1);
        while (nb0) {
            int c = __ffs(nb0) - 1; nb0 &= nb0 - 1;
            float4 v = __ldcs(&Drow[c * 32 + lane]);
            PROC_CHUNK(c, v);
        }
        while (nb1) {
            int c = 32 + __ffs(nb1) - 1; nb1 &= nb1 - 1;
            float4 v = __ldcs(&Drow[c * 32 + lane]);
            PROC_CHUNK(c, v);
        }
    }

    if (lane < KSEL) {
        int idx;
#pragma unroll
        for (int p = 0; p < KSEL; p++)
            if (p == lane) idx = (int)(L[p] & 0xffffffffu);
        g_inds[row * KSEL + lane] = idx;
        atomicAdd(&g_de[idx], 1);
    }
}

// ---------------- kScat: fused KNN scatter + local edge sums ----------------
__global__ __launch_bounds__(256) void kScat() {
    int tid = threadIdx.x;
    if (blockIdx.x >= BNN / 4) {
        int e = (blockIdx.x - BNN / 4) * 4 + (tid >> 6);
        int c = tid & 63;
        if (e < NLOC) {
            int b  = e / 196, le = e % 196;
            int er = le / 14, ec = le % 14;
            int base = b * NROWS + er * 2 * 32 + ec * 2;
            float s = 0.0f;
#pragma unroll
            for (int dr = 0; dr < 5; dr++)
#pragma unroll
                for (int dc = 0; dc < 5; dc++)
                    s += g_u[(base + dr * 32 + dc) * CC + c];
            g_sloc[e * CC + c] = s * (1.0f / 25.0f);
        }
        return;
    }

    __shared__ int si[4 * KSEL];
    int node0 = blockIdx.x * 4;
    if (tid < 4 * KSEL) si[tid] = g_inds[node0 * KSEL + tid];
    __syncthreads();
    int n = tid >> 6, c = tid & 63;
    float uv = g_u[(node0 + n) * CC + c];
#pragma unroll
    for (int m = 0; m < KSEL; m++)
        atomicAdd(&g_sknn[si[n * KSEL + m] * CC + c], uv);
}

// ---------------- kE: gather z (fused 1/DE) + BN stats ----------------
__global__ __launch_bounds__(256) void kE() {
    __shared__ int si[4 * KSEL];
    __shared__ float sdr[4 * KSEL];
    __shared__ float red[256], red2[256];
    int tid = threadIdx.x;
    int node0 = blockIdx.x * 4;
    if (tid < 4 * KSEL) si[tid] = g_inds[node0 * KSEL + tid];
    __syncthreads();
    if (tid < 4 * KSEL) sdr[tid] = 1.0f / (float)g_de[si[tid]];
    __syncthreads();
    int n = tid >> 6, c = tid & 63;
    int node = node0 + n;

    float acc = 0.0f;
#pragma unroll
    for (int m = 0; m < KSEL; m++)
        acc += g_sknn[si[n * KSEL + m] * CC + c] * sdr[n * KSEL + m];

    int ln = node & (NROWS - 1);
    int r = ln >> 5, cc2 = ln & 31;
    int b = node >> 10;
    int sr0 = r - 4; if (sr0 < 0) sr0 = 0; sr0 += (sr0 & 1);
    int sr1 = r;     if (sr1 > 26) sr1 = 26; sr1 -= (sr1 & 1);
    int sc0 = cc2 - 4; if (sc0 < 0) sc0 = 0; sc0 += (sc0 & 1);
    int sc1 = cc2;     if (sc1 > 26) sc1 = 26; sc1 -= (sc1 & 1);
    for (int sr = sr0; sr <= sr1; sr += 2)
        for (int sc = sc0; sc <= sc1; sc += 2)
            acc += g_sloc[(b * 196 + (sr >> 1) * 14 + (sc >> 1)) * CC + c];

    float z = acc * dv2f(node);
    g_z[node * CC + c] = z;

    red[tid] = z; red2[tid] = z * z;
    __syncthreads();
    if (tid < 128) { red[tid] += red[tid + 128]; red2[tid] += red2[tid + 128]; }
    __syncthreads();
    if (tid < 64) {
        atomicAdd(&g_stats[tid],      red[tid]  + red[tid + 64]);
        atomicAdd(&g_stats[64 + tid], red2[tid] + red2[tid + 64]);
    }
}

// ---------------- kG ----------------
__global__ void kG(const float* __restrict__ x,
                   const float* __restrict__ gamma,
                   const float* __restrict__ beta,
                   float* __restrict__ out) {
    int i = blockIdx.x * 256 + threadIdx.x;
    int c = i & 63;
    float mu  = g_stats[c]      * (1.0f / (float)BNN);
    float ex2 = g_stats[64 + c] * (1.0f / (float)BNN);
    float var = ex2 - mu * mu;
    float rstd = 1.0f / sqrtf(var + 1e-5f);
    float zn = (g_z[i] - mu) * rstd * gamma[c] + beta[c];
    out[i] = fmaxf(zn, 0.0f) + x[i];
}

// ---------------- launch ----------------
extern "C" void kernel_launch(void* const* d_in, const int* in_sizes, int n_in,
                              void* d_out, int out_size) {
    const float* x     = (const float*)d_in[0];
    const float* W     = (const float*)d_in[1];
    const float* bconv = (const float*)d_in[2];
    const float* gamma = (const float*)d_in[3];
    const float* beta  = (const float*)d_in[4];
    float* out = (float*)d_out;

    cudaFuncSetAttribute(kB, cudaFuncAttributeMaxDynamicSharedMemorySize, SMEM_KB);

    kA    <<<BNN / 4 + 2048, 256>>>(x, W, bconv);
    kB    <<<2080, 256, SMEM_KB>>>(x);
    kC    <<<BNN / KC_WARPS, 32 * KC_WARPS>>>();
    kScat <<<BNN / 4 + 392, 256>>>();
    kE    <<<BNN / 4, 256>>>();
    kG    <<<2048, 256>>>(x, gamma, beta, out);
}